// round 3
// baseline (speedup 1.0000x reference)
#include <cuda_runtime.h>
#include <cstdint>

#define PLANE 65536   // 256*256

// Pre-transposed weights: wT[k][c][o]
__device__ float g_wT[9][64][64];

__global__ void wt_transpose(const float* __restrict__ wgt)
{
    int i = blockIdx.x * 256 + threadIdx.x;   // 36864 elems, coalesced read
    if (i < 36864) {
        int o = i / 576;
        int r = i - o * 576;
        int c = r / 9;
        int k = r - c * 9;
        g_wT[k][c][o] = wgt[i];
    }
}

// CTA = 128 contiguous pixels x 64 output channels. 256 threads.
// Per tap: stage w_k[64c][64o] (native layout) + gather val[64c][128p] in SMEM,
// then GEMM with o-PAIR packed f32x2 accumulators:
//   warp = o-group (weight LDS fully broadcast), thread = 8o x 4p.
__global__ __launch_bounds__(256, 2)
void dcn_main(const float* __restrict__ x,
              const float* __restrict__ off,
              const float* __restrict__ msk,
              float* __restrict__ out)
{
    extern __shared__ float smem[];
    float* wk  = smem;           // [64c][64o]  16384 B
    float* val = smem + 4096;    // [64c][128p] 32768 B

    const int t   = threadIdx.x;
    const int blk = blockIdx.x;          // 1024 CTAs
    const int b   = blk >> 9;
    const int h   = (blk >> 1) & 255;
    const int w0  = (blk & 1) << 7;
    const int p0  = (h << 8) | w0;

    // GEMM roles: warp og, lane pg
    const int og = t >> 5;               // 0..7  (o-block of 8)
    const int pg = t & 31;               // 0..31 (pixel, +{0,32,64,96})

    // gather roles: 2 threads per pixel, 32 channels each
    const int gpix = t & 127;
    const int c0g  = (t >> 7) << 5;      // 0 or 32
    const int gw   = w0 + gpix;

    const float* offp = off + (size_t)b * 18 * PLANE + p0 + gpix;
    const float* mskp = msk + (size_t)b * 9  * PLANE + p0 + gpix;
    const float* xb   = x + ((size_t)b * 64 + c0g) * PLANE;
    const float* wsrc = &g_wT[0][0][0];

    unsigned long long acc[4][4];        // [o-pair][pixel]
#pragma unroll
    for (int i = 0; i < 4; ++i)
#pragma unroll
        for (int j = 0; j < 4; ++j) acc[i][j] = 0ULL;

    for (int k = 0; k < 9; ++k) {
        __syncthreads();   // previous GEMM readers done

        // ---- stage weights (straight coalesced copy, native [c][o]) ----
        const float4* ws = (const float4*)(wsrc + k * 4096);
        float4* wd = (float4*)wk;
#pragma unroll
        for (int j = 0; j < 4; ++j) wd[j * 256 + t] = ws[j * 256 + t];

        // ---- bilinear gather ----
        const float oy = __ldg(offp + (2 * k)     * PLANE);
        const float ox = __ldg(offp + (2 * k + 1) * PLANE);
        const float m  = __ldg(mskp + k * PLANE);
        const int ky = k / 3;
        const int kx = k - ky * 3;

        const float py  = oy + (float)(h  - 1 + ky);
        const float px  = ox + (float)(gw - 1 + kx);
        const float y0f = floorf(py);
        const float x0f = floorf(px);
        const float dy = py - y0f;
        const float dx = px - x0f;
        const int y0 = (int)y0f, x0 = (int)x0f;
        const int y1 = y0 + 1,   x1 = x0 + 1;
        const bool vy0 = (unsigned)y0 < 256u;
        const bool vy1 = (unsigned)y1 < 256u;
        const bool vx0 = (unsigned)x0 < 256u;
        const bool vx1 = (unsigned)x1 < 256u;
        const int cy0 = min(max(y0, 0), 255);
        const int cy1 = min(max(y1, 0), 255);
        const int cx0 = min(max(x0, 0), 255);
        const int cx1 = min(max(x1, 0), 255);
        const float a00 = (vy0 && vx0) ? (1.f - dy) * (1.f - dx) * m : 0.f;
        const float a01 = (vy0 && vx1) ? (1.f - dy) * dx         * m : 0.f;
        const float a10 = (vy1 && vx0) ? dy         * (1.f - dx) * m : 0.f;
        const float a11 = (vy1 && vx1) ? dy         * dx         * m : 0.f;
        const int i00 = (cy0 << 8) | cx0;
        const int i01 = (cy0 << 8) | cx1;
        const int i10 = (cy1 << 8) | cx0;
        const int i11 = (cy1 << 8) | cx1;

        float* vcol = val + gpix;
#pragma unroll 4
        for (int c = 0; c < 32; ++c) {
            const float* xp = xb + (size_t)c * PLANE;
            const float v00 = __ldg(xp + i00);
            const float v01 = __ldg(xp + i01);
            const float v10 = __ldg(xp + i10);
            const float v11 = __ldg(xp + i11);
            vcol[(c0g + c) << 7] = a00 * v00 + a01 * v01 + a10 * v10 + a11 * v11;
        }

        __syncthreads();

        // ---- GEMM: thread = 8 o (4 native u64 pairs) x 4 p ----
        const float* wrow = wk + (og << 3);      // broadcast within warp
        const float* vrow = val + pg;
#pragma unroll 2
        for (int c = 0; c < 64; ++c) {
            const ulonglong2 wq0 = *(const ulonglong2*)(wrow + (c << 6));
            const ulonglong2 wq1 = *(const ulonglong2*)(wrow + (c << 6) + 4);
            const float v0 = vrow[(c << 7)];
            const float v1 = vrow[(c << 7) + 32];
            const float v2 = vrow[(c << 7) + 64];
            const float v3 = vrow[(c << 7) + 96];
            unsigned long long d0, d1, d2, d3;
            asm("mov.b64 %0, {%1, %1};" : "=l"(d0) : "f"(v0));
            asm("mov.b64 %0, {%1, %1};" : "=l"(d1) : "f"(v1));
            asm("mov.b64 %0, {%1, %1};" : "=l"(d2) : "f"(v2));
            asm("mov.b64 %0, {%1, %1};" : "=l"(d3) : "f"(v3));

            asm("fma.rn.f32x2 %0, %1, %2, %0;" : "+l"(acc[0][0]) : "l"(wq0.x), "l"(d0));
            asm("fma.rn.f32x2 %0, %1, %2, %0;" : "+l"(acc[0][1]) : "l"(wq0.x), "l"(d1));
            asm("fma.rn.f32x2 %0, %1, %2, %0;" : "+l"(acc[0][2]) : "l"(wq0.x), "l"(d2));
            asm("fma.rn.f32x2 %0, %1, %2, %0;" : "+l"(acc[0][3]) : "l"(wq0.x), "l"(d3));
            asm("fma.rn.f32x2 %0, %1, %2, %0;" : "+l"(acc[1][0]) : "l"(wq0.y), "l"(d0));
            asm("fma.rn.f32x2 %0, %1, %2, %0;" : "+l"(acc[1][1]) : "l"(wq0.y), "l"(d1));
            asm("fma.rn.f32x2 %0, %1, %2, %0;" : "+l"(acc[1][2]) : "l"(wq0.y), "l"(d2));
            asm("fma.rn.f32x2 %0, %1, %2, %0;" : "+l"(acc[1][3]) : "l"(wq0.y), "l"(d3));
            asm("fma.rn.f32x2 %0, %1, %2, %0;" : "+l"(acc[2][0]) : "l"(wq1.x), "l"(d0));
            asm("fma.rn.f32x2 %0, %1, %2, %0;" : "+l"(acc[2][1]) : "l"(wq1.x), "l"(d1));
            asm("fma.rn.f32x2 %0, %1, %2, %0;" : "+l"(acc[2][2]) : "l"(wq1.x), "l"(d2));
            asm("fma.rn.f32x2 %0, %1, %2, %0;" : "+l"(acc[2][3]) : "l"(wq1.x), "l"(d3));
            asm("fma.rn.f32x2 %0, %1, %2, %0;" : "+l"(acc[3][0]) : "l"(wq1.y), "l"(d0));
            asm("fma.rn.f32x2 %0, %1, %2, %0;" : "+l"(acc[3][1]) : "l"(wq1.y), "l"(d1));
            asm("fma.rn.f32x2 %0, %1, %2, %0;" : "+l"(acc[3][2]) : "l"(wq1.y), "l"(d2));
            asm("fma.rn.f32x2 %0, %1, %2, %0;" : "+l"(acc[3][3]) : "l"(wq1.y), "l"(d3));
        }
    }

    // ---- epilogue: direct coalesced STG.32 (lanes = contiguous pixels) ----
    float* ob = out + (size_t)b * 64 * PLANE + p0 + pg;
#pragma unroll
    for (int op = 0; op < 4; ++op) {
        const int o0 = (og << 3) + (op << 1);
        float* r0 = ob + (size_t)o0 * PLANE;
        float* r1 = ob + (size_t)(o0 + 1) * PLANE;
#pragma unroll
        for (int pi = 0; pi < 4; ++pi) {
            float lo, hi;
            asm("mov.b64 {%0, %1}, %2;" : "=f"(lo), "=f"(hi) : "l"(acc[op][pi]));
            r0[pi << 5] = lo;
            r1[pi << 5] = hi;
        }
    }
}

extern "C" void kernel_launch(void* const* d_in, const int* in_sizes, int n_in,
                              void* d_out, int out_size)
{
    const float* x   = (const float*)d_in[0];
    const float* wgt = (const float*)d_in[1];
    const float* off = (const float*)d_in[2];
    const float* msk = (const float*)d_in[3];
    float* out = (float*)d_out;

    wt_transpose<<<144, 256>>>(wgt);

    cudaFuncSetAttribute(dcn_main, cudaFuncAttributeMaxDynamicSharedMemorySize, 49152);
    dcn_main<<<1024, 256, 49152>>>(x, off, msk, out);
}